// round 1
// baseline (speedup 1.0000x reference)
#include <cuda_runtime.h>
#include <cuda_bf16.h>
#include <cstdint>

// Problem constants
#define NB    32
#define CIN   256
#define COUT  256
#define TT    128
#define VV    25
#define KK    3
#define KCOUT 768          // K*COUT
#define TVN   3200         // T*V
#define NTV   102400       // N*T*V
#define BN_EPS 1e-5f

// Scratch (device globals: allocation-free per harness rules)
__device__ float g_y1[(size_t)NB * KCOUT * TVN];   // [n][o][t][v]  314 MB
__device__ float g_y [(size_t)NB * COUT * TVN];    // [n][c][t][w]  105 MB
__device__ float g_sum[COUT];
__device__ float g_sqsum[COUT];

// ---------------------------------------------------------------------------
// Kernel 0: zero BN stat accumulators
// ---------------------------------------------------------------------------
__global__ void zero_stats_kernel() {
    int t = threadIdx.x;
    if (t < COUT) { g_sum[t] = 0.0f; g_sqsum[t] = 0.0f; }
}

// ---------------------------------------------------------------------------
// Kernel 1: y1[o, n*T*V] = W[o, ci] @ x[ci, n*T*V] + b[o]     (TF32 mma.sync)
//   M=768, N=102400, K=256.  Block tile 128x128, BK=32, 8 warps (4M x 2N),
//   warp tile 32x64 via m16n8k8 tf32.
// ---------------------------------------------------------------------------
__device__ __forceinline__ uint32_t f2tf(float f) {
    uint32_t r;
    asm("cvt.rna.tf32.f32 %0, %1;" : "=r"(r) : "f"(f));
    return r;
}

__device__ __forceinline__ void mma_tf32(float c[4], const uint32_t a[4], uint32_t b0, uint32_t b1) {
    asm volatile(
        "mma.sync.aligned.m16n8k8.row.col.f32.tf32.tf32.f32 "
        "{%0,%1,%2,%3}, {%4,%5,%6,%7}, {%8,%9}, {%0,%1,%2,%3};\n"
        : "+f"(c[0]), "+f"(c[1]), "+f"(c[2]), "+f"(c[3])
        : "r"(a[0]), "r"(a[1]), "r"(a[2]), "r"(a[3]), "r"(b0), "r"(b1));
}

#define LDA_S 36    // padded smem stride for A tile (conflict-free, 16B aligned)
#define LDB_S 136   // padded smem stride for B tile

__global__ __launch_bounds__(256) void gemm_kernel(
    const float* __restrict__ x, const float* __restrict__ W, const float* __restrict__ bias)
{
    __shared__ uint32_t As[128 * LDA_S];
    __shared__ uint32_t Bs[32 * LDB_S];

    const int m0     = blockIdx.x * 128;        // o tile (6 tiles)
    const int ct     = blockIdx.y;              // column tile (800 tiles)
    const int n      = ct / 25;
    const int tvbase = (ct % 25) * 128;

    const float* xB = x + (size_t)n * (CIN * TVN) + tvbase;  // B[ci][localcol] stride TVN

    const int tid  = threadIdx.x;
    const int lane = tid & 31;
    const int warp = tid >> 5;
    const int wm   = warp >> 1;   // 0..3  (M)
    const int wn   = warp & 1;    // 0..1  (N)
    const int g    = lane >> 2;
    const int k4   = lane & 3;

    float acc[2][8][4];
    #pragma unroll
    for (int i = 0; i < 2; i++)
        #pragma unroll
        for (int j = 0; j < 8; j++)
            #pragma unroll
            for (int r = 0; r < 4; r++) acc[i][j][r] = 0.0f;

    for (int kk = 0; kk < CIN; kk += 32) {
        // Load A tile: 128 rows x 32 cols of W
        {
            const int r  = tid >> 3;
            const int cv = (tid & 7) * 4;
            #pragma unroll
            for (int p = 0; p < 4; p++) {
                const int row = r + 32 * p;
                const float4 v = *(const float4*)(W + (size_t)(m0 + row) * CIN + kk + cv);
                uint32_t* d = &As[row * LDA_S + cv];
                d[0] = f2tf(v.x); d[1] = f2tf(v.y); d[2] = f2tf(v.z); d[3] = f2tf(v.w);
            }
        }
        // Load B tile: 32 rows (ci) x 128 cols
        {
            const int r  = tid >> 5;
            const int cv = (tid & 31) * 4;
            #pragma unroll
            for (int p = 0; p < 4; p++) {
                const int row = r + 8 * p;
                const float4 v = *(const float4*)(xB + (size_t)(kk + row) * TVN + cv);
                uint32_t* d = &Bs[row * LDB_S + cv];
                d[0] = f2tf(v.x); d[1] = f2tf(v.y); d[2] = f2tf(v.z); d[3] = f2tf(v.w);
            }
        }
        __syncthreads();

        #pragma unroll
        for (int k8 = 0; k8 < 4; k8++) {
            uint32_t a[2][4], b[8][2];
            #pragma unroll
            for (int i = 0; i < 2; i++) {
                const uint32_t* base = &As[(wm * 32 + i * 16 + g) * LDA_S + k8 * 8 + k4];
                a[i][0] = base[0];
                a[i][1] = base[8 * LDA_S];
                a[i][2] = base[4];
                a[i][3] = base[8 * LDA_S + 4];
            }
            #pragma unroll
            for (int j = 0; j < 8; j++) {
                const uint32_t* base = &Bs[(k8 * 8 + k4) * LDB_S + wn * 64 + j * 8 + g];
                b[j][0] = base[0];
                b[j][1] = base[4 * LDB_S];
            }
            #pragma unroll
            for (int i = 0; i < 2; i++)
                #pragma unroll
                for (int j = 0; j < 8; j++)
                    mma_tf32(acc[i][j], a[i], b[j][0], b[j][1]);
        }
        __syncthreads();
    }

    // Epilogue: +bias, store to g_y1[n][o][tv]
    float* yout = g_y1 + (size_t)n * (KCOUT * TVN) + tvbase;
    #pragma unroll
    for (int i = 0; i < 2; i++) {
        #pragma unroll
        for (int h = 0; h < 2; h++) {
            const int row = m0 + wm * 32 + i * 16 + g + h * 8;
            const float bv = bias[row];
            #pragma unroll
            for (int j = 0; j < 8; j++) {
                const int col = wn * 64 + j * 8 + k4 * 2;
                float2 val;
                val.x = acc[i][j][h * 2 + 0] + bv;
                val.y = acc[i][j][h * 2 + 1] + bv;
                *(float2*)(yout + (size_t)row * TVN + col) = val;
            }
        }
    }
}

// ---------------------------------------------------------------------------
// Kernel 2: y[n,c,t,w] = sum_{k,v} y1[n, k*COUT+c, t, v] * A[k,v,w]
//           + accumulate per-channel BN stats (sum, sumsq) via atomics.
//   Block = (c, n), 128 threads (one t each, 25 accumulators in registers).
// ---------------------------------------------------------------------------
__global__ __launch_bounds__(128) void contract_kernel(const float* __restrict__ A)
{
    __shared__ float As[KK][VV][28];   // padded rows: 112B -> 16B aligned, vec LDS
    __shared__ float red_s[4], red_s2[4];

    const int c = blockIdx.x;
    const int n = blockIdx.y;
    const int tid = threadIdx.x;   // == t (0..127)

    for (int i = tid; i < KK * VV * VV; i += 128) {
        int k = i / (VV * VV);
        int rem = i % (VV * VV);
        As[k][rem / VV][rem % VV] = A[i];
    }
    __syncthreads();

    const float* ybase = g_y1 + (size_t)n * (KCOUT * TVN) + (size_t)c * TVN + tid * VV;

    float acc[VV];
    #pragma unroll
    for (int w = 0; w < VV; w++) acc[w] = 0.0f;

    #pragma unroll
    for (int k = 0; k < KK; k++) {
        const float* yr = ybase + (size_t)k * (COUT * TVN);
        float vals[VV];
        #pragma unroll
        for (int v = 0; v < VV; v++) vals[v] = yr[v];
        #pragma unroll
        for (int v = 0; v < VV; v++) {
            const float val = vals[v];
            #pragma unroll
            for (int w = 0; w < VV; w++) acc[w] += val * As[k][v][w];
        }
    }

    float* out = g_y + ((size_t)n * COUT + c) * TVN + tid * VV;
    float s = 0.0f, s2 = 0.0f;
    #pragma unroll
    for (int w = 0; w < VV; w++) {
        out[w] = acc[w];
        s  += acc[w];
        s2 += acc[w] * acc[w];
    }

    // Block reduce then atomics
    #pragma unroll
    for (int off = 16; off > 0; off >>= 1) {
        s  += __shfl_down_sync(0xFFFFFFFFu, s,  off);
        s2 += __shfl_down_sync(0xFFFFFFFFu, s2, off);
    }
    const int lane = tid & 31, warp = tid >> 5;
    if (lane == 0) { red_s[warp] = s; red_s2[warp] = s2; }
    __syncthreads();
    if (tid == 0) {
        float S  = red_s[0]  + red_s[1]  + red_s[2]  + red_s[3];
        float S2 = red_s2[0] + red_s2[1] + red_s2[2] + red_s2[3];
        atomicAdd(&g_sum[c],   S);
        atomicAdd(&g_sqsum[c], S2);
    }
}

// ---------------------------------------------------------------------------
// Kernel 3: BN finalize + affine + ReLU (float4 elementwise)
// ---------------------------------------------------------------------------
__global__ __launch_bounds__(256) void bn_kernel(
    const float* __restrict__ gamma, const float* __restrict__ beta, float* __restrict__ out)
{
    const size_t i = (size_t)blockIdx.x * 256 + threadIdx.x;   // float4 index
    const int c = (int)((i * 4) / TVN) % COUT;                 // 4 | TVN -> uniform in vec

    const float cnt_inv = 1.0f / (float)NTV;
    const float mu  = g_sum[c] * cnt_inv;
    const float var = g_sqsum[c] * cnt_inv - mu * mu;
    const float inv = rsqrtf(var + BN_EPS);
    const float scale = gamma[c] * inv;
    const float shift = beta[c] - mu * scale;

    float4 v = ((const float4*)g_y)[i];
    v.x = fmaxf(v.x * scale + shift, 0.0f);
    v.y = fmaxf(v.y * scale + shift, 0.0f);
    v.z = fmaxf(v.z * scale + shift, 0.0f);
    v.w = fmaxf(v.w * scale + shift, 0.0f);
    ((float4*)out)[i] = v;
}

// ---------------------------------------------------------------------------
extern "C" void kernel_launch(void* const* d_in, const int* in_sizes, int n_in,
                              void* d_out, int out_size)
{
    const float* x     = (const float*)d_in[0];   // [32,256,128,25]
    const float* A     = (const float*)d_in[1];   // [3,25,25]
    const float* W     = (const float*)d_in[2];   // [768,256]
    const float* b     = (const float*)d_in[3];   // [768]
    const float* gamma = (const float*)d_in[4];   // [256]
    const float* beta  = (const float*)d_in[5];   // [256]

    zero_stats_kernel<<<1, 256>>>();

    dim3 g1(6, 800);
    gemm_kernel<<<g1, 256>>>(x, W, b);

    dim3 g2(COUT, NB);
    contract_kernel<<<g2, 128>>>(A);

    const int nvec = (NB * COUT * TVN) / 4;       // 6,553,600
    bn_kernel<<<nvec / 256, 256>>>(gamma, beta, (float*)d_out);
}